// round 1
// baseline (speedup 1.0000x reference)
#include <cuda_runtime.h>
#include <math.h>

// Problem constants
#define B_DIM 4
#define S_DIM 2048
#define T_DIM 256
#define H_DIM 2048
#define NHEAD 16
#define HD_DIM 128

// GEMM tile config
#define BM 128
#define BN 128
#define BK 16

// ---------------------------------------------------------------------------
// Scratch (device globals — no allocation allowed)
// ---------------------------------------------------------------------------
__device__ float g_Q[8192 * 2048];            // Q projection  [B*S, H]
__device__ float g_K[1024 * 2048];            // K projection  [B*T, H]
__device__ float g_Vt[B_DIM * NHEAD * HD_DIM * T_DIM];  // V transposed [b,h,d,t]
__device__ float g_S[B_DIM * NHEAD * S_DIM * T_DIM];    // scores/probs [z,s,t]
__device__ float g_C[8192 * 2048];            // attention context [B*S, H]
__device__ float g_D[8192 * 2048];            // O-proj output (pre-LN)

// ---------------------------------------------------------------------------
// Generic TN GEMM: C = A[M,K] * B[N,K]^T (+ epilogue per MODE)
//   MODE 0: proj        — C[row*ldc+col] = acc + bias[col]
//   MODE 1: V-proj      — scatter to g_Vt[((b*NH+h)*HD+d)*T + t] (+bias)
//   MODE 2: scores      — scale, clip ±50, mask -> -50; batched over z=(b,h)
//   MODE 3: PV          — scatter ctx to [b*S+s, h*HD+d]; batched over z
// All of M, N multiples of 128; K multiple of 16. No bounds checks.
// ---------------------------------------------------------------------------
template<int MODE>
__global__ void __launch_bounds__(256, 2)
gemm_kernel(const float* __restrict__ Ag, const float* __restrict__ Bg,
            const float* __restrict__ bias, const int* __restrict__ mask,
            float* __restrict__ Cg, int K, int lda, int ldb, int ldc)
{
    const int tid = threadIdx.x;
    const int tx = tid & 15;        // col group
    const int ty = tid >> 4;        // row group
    const int m0 = blockIdx.y * BM;
    const int n0 = blockIdx.x * BN;

    const float* A = Ag;
    const float* Bm = Bg;
    int bb = 0, hh = 0;
    if (MODE == 2) {
        bb = blockIdx.z >> 4; hh = blockIdx.z & 15;
        A  = Ag + (size_t)bb * S_DIM * H_DIM + hh * HD_DIM;
        Bm = Bg + (size_t)bb * T_DIM * H_DIM + hh * HD_DIM;
    } else if (MODE == 3) {
        bb = blockIdx.z >> 4; hh = blockIdx.z & 15;
        A  = Ag + (size_t)blockIdx.z * S_DIM * T_DIM;
        Bm = Bg + (size_t)blockIdx.z * HD_DIM * T_DIM;
    }

    __shared__ float As[BK][BM + 4];
    __shared__ float Bs[BK][BN + 4];

    float acc[8][8];
#pragma unroll
    for (int i = 0; i < 8; i++)
#pragma unroll
        for (int j = 0; j < 8; j++) acc[i][j] = 0.f;

    const int lrow0 = tid >> 2;          // 0..63
    const int lkc   = (tid & 3) << 2;    // 0,4,8,12

    for (int kt = 0; kt < K; kt += BK) {
#pragma unroll
        for (int half = 0; half < 2; half++) {
            int row = lrow0 + half * 64;
            float4 a4 = *(const float4*)(A + (size_t)(m0 + row) * lda + kt + lkc);
            As[lkc + 0][row] = a4.x; As[lkc + 1][row] = a4.y;
            As[lkc + 2][row] = a4.z; As[lkc + 3][row] = a4.w;
            float4 b4 = *(const float4*)(Bm + (size_t)(n0 + row) * ldb + kt + lkc);
            Bs[lkc + 0][row] = b4.x; Bs[lkc + 1][row] = b4.y;
            Bs[lkc + 2][row] = b4.z; Bs[lkc + 3][row] = b4.w;
        }
        __syncthreads();
#pragma unroll
        for (int k = 0; k < BK; k++) {
            float4 a0 = *(const float4*)&As[k][ty * 4];
            float4 a1 = *(const float4*)&As[k][64 + ty * 4];
            float4 b0 = *(const float4*)&Bs[k][tx * 4];
            float4 b1 = *(const float4*)&Bs[k][64 + tx * 4];
            float av[8] = {a0.x, a0.y, a0.z, a0.w, a1.x, a1.y, a1.z, a1.w};
            float bv[8] = {b0.x, b0.y, b0.z, b0.w, b1.x, b1.y, b1.z, b1.w};
#pragma unroll
            for (int i = 0; i < 8; i++)
#pragma unroll
                for (int j = 0; j < 8; j++)
                    acc[i][j] = fmaf(av[i], bv[j], acc[i][j]);
        }
        __syncthreads();
    }

    // Epilogue
#pragma unroll
    for (int i = 0; i < 8; i++) {
        int row = m0 + (i >> 2) * 64 + ty * 4 + (i & 3);
#pragma unroll
        for (int jh = 0; jh < 2; jh++) {
            int col = n0 + jh * 64 + tx * 4;
            if (MODE == 0) {
                float4 bb4 = *(const float4*)(bias + col);
                float4 o = make_float4(acc[i][jh*4+0] + bb4.x,
                                       acc[i][jh*4+1] + bb4.y,
                                       acc[i][jh*4+2] + bb4.z,
                                       acc[i][jh*4+3] + bb4.w);
                *(float4*)(Cg + (size_t)row * ldc + col) = o;
            } else if (MODE == 1) {
                int bidx = row >> 8;       // / T
                int t    = row & 255;      // % T
#pragma unroll
                for (int j = 0; j < 4; j++) {
                    int c  = col + j;
                    int hq = c >> 7;       // / HD
                    int dq = c & 127;      // % HD
                    float v = acc[i][jh*4+j] + bias[c];
                    Cg[(((size_t)bidx * NHEAD + hq) * HD_DIM + dq) * T_DIM + t] = v;
                }
            } else if (MODE == 2) {
                const float invs = 0.08838834764831845f;  // 1/sqrt(128)
                float4 o;
                float* po = &o.x;
#pragma unroll
                for (int j = 0; j < 4; j++) {
                    float v = acc[i][jh*4+j] * invs;
                    v = fminf(fmaxf(v, -50.f), 50.f);
                    int att = mask[bb * T_DIM + col + j];
                    po[j] = att ? v : -50.f;
                }
                *(float4*)(Cg + (size_t)blockIdx.z * S_DIM * T_DIM
                              + (size_t)row * T_DIM + col) = o;
            } else {  // MODE 3: ctx scatter
                float4 o = make_float4(acc[i][jh*4+0], acc[i][jh*4+1],
                                       acc[i][jh*4+2], acc[i][jh*4+3]);
                *(float4*)(Cg + (size_t)(bb * S_DIM + row) * H_DIM
                              + hh * HD_DIM + col) = o;
            }
        }
    }
}

// ---------------------------------------------------------------------------
// Softmax: one warp per row of 256 scores (in place on g_S)
// ---------------------------------------------------------------------------
__global__ void softmax_kernel(float* __restrict__ S)
{
    int gw   = (blockIdx.x * blockDim.x + threadIdx.x) >> 5;  // row index
    int lane = threadIdx.x & 31;
    float* p = S + (size_t)gw * T_DIM;

    float4 v0 = *(const float4*)(p + lane * 4);
    float4 v1 = *(const float4*)(p + 128 + lane * 4);
    float v[8] = {v0.x, v0.y, v0.z, v0.w, v1.x, v1.y, v1.z, v1.w};

    float mx = v[0];
#pragma unroll
    for (int i = 1; i < 8; i++) mx = fmaxf(mx, v[i]);
#pragma unroll
    for (int o = 16; o; o >>= 1) mx = fmaxf(mx, __shfl_xor_sync(0xffffffffu, mx, o));

    float s = 0.f;
#pragma unroll
    for (int i = 0; i < 8; i++) { v[i] = __expf(v[i] - mx); s += v[i]; }
#pragma unroll
    for (int o = 16; o; o >>= 1) s += __shfl_xor_sync(0xffffffffu, s, o);

    float inv = 1.f / s;
#pragma unroll
    for (int i = 0; i < 8; i++) v[i] *= inv;

    *(float4*)(p + lane * 4)       = make_float4(v[0], v[1], v[2], v[3]);
    *(float4*)(p + 128 + lane * 4) = make_float4(v[4], v[5], v[6], v[7]);
}

// ---------------------------------------------------------------------------
// LayerNorm: one block (256 threads) per row of 2048; applies residual_scale
// ---------------------------------------------------------------------------
__device__ __forceinline__ float block_sum(float v)
{
    __shared__ float red[8];
#pragma unroll
    for (int o = 16; o; o >>= 1) v += __shfl_xor_sync(0xffffffffu, v, o);
    int w = threadIdx.x >> 5;
    if ((threadIdx.x & 31) == 0) red[w] = v;
    __syncthreads();
    float t = (threadIdx.x < 8) ? red[threadIdx.x] : 0.f;
    if (threadIdx.x < 32) {
#pragma unroll
        for (int o = 4; o; o >>= 1) t += __shfl_xor_sync(0xffffffffu, t, o);
        if (threadIdx.x == 0) red[0] = t;
    }
    __syncthreads();
    float r = red[0];
    __syncthreads();
    return r;
}

__global__ void ln_kernel(const float* __restrict__ D, const float* __restrict__ gamma,
                          const float* __restrict__ beta, const float* __restrict__ rsp,
                          float* __restrict__ out)
{
    int row = blockIdx.x;
    int tid = threadIdx.x;
    float rs = fminf(fmaxf(rsp[0], 0.f), 0.3f);

    const float* d = D + (size_t)row * H_DIM;
    float4 u0 = *(const float4*)(d + tid * 4);
    float4 u1 = *(const float4*)(d + 1024 + tid * 4);
    float x[8] = {rs*u0.x, rs*u0.y, rs*u0.z, rs*u0.w,
                  rs*u1.x, rs*u1.y, rs*u1.z, rs*u1.w};

    float ps = 0.f;
#pragma unroll
    for (int i = 0; i < 8; i++) ps += x[i];
    float mean = block_sum(ps) * (1.f / 2048.f);

    float pv = 0.f;
#pragma unroll
    for (int i = 0; i < 8; i++) { float dd = x[i] - mean; pv += dd * dd; }
    float var = block_sum(pv) * (1.f / 2048.f);
    float inv = rsqrtf(var + 1e-5f);

    float4 gz0 = *(const float4*)(gamma + tid * 4);
    float4 gz1 = *(const float4*)(gamma + 1024 + tid * 4);
    float4 bz0 = *(const float4*)(beta + tid * 4);
    float4 bz1 = *(const float4*)(beta + 1024 + tid * 4);

    float* o = out + (size_t)row * H_DIM;
    *(float4*)(o + tid * 4) = make_float4(
        (x[0]-mean)*inv*gz0.x + bz0.x, (x[1]-mean)*inv*gz0.y + bz0.y,
        (x[2]-mean)*inv*gz0.z + bz0.z, (x[3]-mean)*inv*gz0.w + bz0.w);
    *(float4*)(o + 1024 + tid * 4) = make_float4(
        (x[4]-mean)*inv*gz1.x + bz1.x, (x[5]-mean)*inv*gz1.y + bz1.y,
        (x[6]-mean)*inv*gz1.z + bz1.z, (x[7]-mean)*inv*gz1.w + bz1.w);
}

// ---------------------------------------------------------------------------
// Launch
// ---------------------------------------------------------------------------
extern "C" void kernel_launch(void* const* d_in, const int* in_sizes, int n_in,
                              void* d_out, int out_size)
{
    const float* hs    = (const float*)d_in[0];
    const float* at    = (const float*)d_in[1];
    const int*   mask  = (const int*)  d_in[2];
    const float* Wq    = (const float*)d_in[3];
    const float* bq    = (const float*)d_in[4];
    const float* Wk    = (const float*)d_in[5];
    const float* bk    = (const float*)d_in[6];
    const float* Wv    = (const float*)d_in[7];
    const float* bv    = (const float*)d_in[8];
    const float* Wo    = (const float*)d_in[9];
    const float* bo    = (const float*)d_in[10];
    const float* gamma = (const float*)d_in[11];
    const float* beta  = (const float*)d_in[12];
    const float* rsp   = (const float*)d_in[13];
    float* out = (float*)d_out;

    float *Q, *Kb, *Vt, *Sb, *Cb, *Db;
    cudaGetSymbolAddress((void**)&Q,  g_Q);
    cudaGetSymbolAddress((void**)&Kb, g_K);
    cudaGetSymbolAddress((void**)&Vt, g_Vt);
    cudaGetSymbolAddress((void**)&Sb, g_S);
    cudaGetSymbolAddress((void**)&Cb, g_C);
    cudaGetSymbolAddress((void**)&Db, g_D);

    // Q projection: [8192,2048] = hs @ Wq^T + bq
    gemm_kernel<0><<<dim3(16, 64, 1), 256>>>(hs, Wq, bq, nullptr, Q,
                                             2048, 2048, 2048, 2048);
    // K projection: [1024,2048]
    gemm_kernel<0><<<dim3(16, 8, 1), 256>>>(at, Wk, bk, nullptr, Kb,
                                            2048, 2048, 2048, 2048);
    // V projection, scattered to [b,h,d,t]
    gemm_kernel<1><<<dim3(16, 8, 1), 256>>>(at, Wv, bv, nullptr, Vt,
                                            2048, 2048, 2048, 0);
    // Scores: per (b,h): [2048,256] = Q_bh @ K_bh^T, scaled/clipped/masked
    gemm_kernel<2><<<dim3(2, 16, 64), 256>>>(Q, Kb, nullptr, mask, Sb,
                                             128, 2048, 2048, 256);
    // Softmax over T=256 per row
    softmax_kernel<<<16384, 256>>>(Sb);
    // PV: per (b,h): [2048,128] = P @ V, scattered to [b*S+s, h*HD+d]
    gemm_kernel<3><<<dim3(1, 16, 64), 256>>>(Sb, Vt, nullptr, nullptr, Cb,
                                             256, 256, 256, 0);
    // O projection
    gemm_kernel<0><<<dim3(16, 64, 1), 256>>>(Cb, Wo, bo, nullptr, Db,
                                             2048, 2048, 2048, 2048);
    // residual scale + LayerNorm
    ln_kernel<<<8192, 256>>>(Db, gamma, beta, rsp, out);
}

// round 4
// speedup vs baseline: 1.8584x; 1.8584x over previous
#include <cuda_runtime.h>
#include <cuda_bf16.h>
#include <cstdint>
#include <math.h>

#define B_DIM 4
#define S_DIM 2048
#define T_DIM 256
#define H_DIM 2048
#define NHEAD 16
#define HD_DIM 128

// GEMM tiling
#define BK 16
#define PITCH 48            // bytes per SMEM row (16 bf16 data + 16B pad -> ldmatrix conflict-free)
#define ATILE 6144          // 128 * 48
#define AHI 0
#define ALO 6144
#define BHI 12288
#define BLO 18432
#define BUFSZ 24576
#define SMEM_BYTES 49152    // two buffers; also reused as fp32 stage (128x68)
#define STAGE_PITCH 68

// ---------------------------------------------------------------------------
// Scratch (device globals — no allocation allowed)
// ---------------------------------------------------------------------------
__device__ float g_Q[8192 * 2048];
__device__ float g_K[1024 * 2048];
__device__ float g_Vt[B_DIM * NHEAD * HD_DIM * T_DIM];
__device__ float g_S[B_DIM * NHEAD * S_DIM * T_DIM];
__device__ float g_C[8192 * 2048];
__device__ float g_D[8192 * 2048];

// ---------------------------------------------------------------------------
// Helpers
// ---------------------------------------------------------------------------
__device__ __forceinline__ uint32_t smem_to_u32(const void* p) {
    uint32_t a;
    asm("{ .reg .u64 t; cvta.to.shared.u64 t, %1; cvt.u32.u64 %0, t; }" : "=r"(a) : "l"(p));
    return a;
}

__device__ __forceinline__ void ldmx4(uint32_t* r, uint32_t addr) {
    asm volatile("ldmatrix.sync.aligned.m8n8.x4.shared.b16 {%0,%1,%2,%3}, [%4];"
                 : "=r"(r[0]), "=r"(r[1]), "=r"(r[2]), "=r"(r[3]) : "r"(addr));
}

__device__ __forceinline__ void mma16816(float* c, const uint32_t* a, const uint32_t* b) {
    asm volatile("mma.sync.aligned.m16n8k16.row.col.f32.bf16.bf16.f32 "
                 "{%0,%1,%2,%3}, {%4,%5,%6,%7}, {%8,%9}, {%0,%1,%2,%3};"
                 : "+f"(c[0]), "+f"(c[1]), "+f"(c[2]), "+f"(c[3])
                 : "r"(a[0]), "r"(a[1]), "r"(a[2]), "r"(a[3]), "r"(b[0]), "r"(b[1]));
}

__device__ __forceinline__ void split_pair(float x0, float x1, uint32_t& hi, uint32_t& lo) {
    __nv_bfloat162 h = __floats2bfloat162_rn(x0, x1);
    float r0 = x0 - __bfloat162float(h.x);
    float r1 = x1 - __bfloat162float(h.y);
    __nv_bfloat162 l = __floats2bfloat162_rn(r0, r1);
    hi = *(uint32_t*)&h;
    lo = *(uint32_t*)&l;
}

// Load 8 fp32 per thread (128 rows x 16 cols over 256 threads)
__device__ __forceinline__ void ldg8(const float* __restrict__ src, int ld, int row0,
                                     int kt, int tid, float4 r[2]) {
    const float* p = src + (size_t)(row0 + (tid >> 1)) * ld + kt + ((tid & 1) << 3);
    r[0] = *(const float4*)p;
    r[1] = *(const float4*)(p + 4);
}

// Split 8 fp32 -> hi/lo bf16 and store one uint4 to each tile
__device__ __forceinline__ void split8(char* buf, int hiOff, int loOff, int tid,
                                       const float4 r[2]) {
    float x[8] = {r[0].x, r[0].y, r[0].z, r[0].w, r[1].x, r[1].y, r[1].z, r[1].w};
    uint32_t hi[4], lo[4];
#pragma unroll
    for (int j = 0; j < 4; j++) split_pair(x[2*j], x[2*j+1], hi[j], lo[j]);
    const int off = (tid >> 1) * PITCH + ((tid & 1) << 4);
    *(uint4*)(buf + hiOff + off) = make_uint4(hi[0], hi[1], hi[2], hi[3]);
    *(uint4*)(buf + loOff + off) = make_uint4(lo[0], lo[1], lo[2], lo[3]);
}

// One BK=16 chunk of MMAs for this warp (3-pass bf16 split)
__device__ __forceinline__ void compute_chunk(uint32_t sbuf, int lane, int mwb, int nwb,
                                              float acc[4][4][4]) {
    uint32_t ah[4][4], al[4][4], bh[4][2], bl[4][2];
    const uint32_t arow = lane & 15;
    const uint32_t akoff = (lane >> 4) << 4;       // 0 or 16 bytes (k half)
#pragma unroll
    for (int mf = 0; mf < 4; mf++) {
        uint32_t ad = sbuf + AHI + (mwb + mf * 16 + arow) * PITCH + akoff;
        ldmx4(ah[mf], ad);
        ldmx4(al[mf], ad + (ALO - AHI));
    }
    const uint32_t brow = (lane & 7) + ((lane >> 4) << 3);
    const uint32_t bkoff = ((lane >> 3) & 1) << 4;
#pragma unroll
    for (int np = 0; np < 2; np++) {
        uint32_t bd = sbuf + BHI + (nwb + np * 16 + brow) * PITCH + bkoff;
        uint32_t r[4];
        ldmx4(r, bd);
        bh[2*np][0] = r[0]; bh[2*np][1] = r[1]; bh[2*np+1][0] = r[2]; bh[2*np+1][1] = r[3];
        ldmx4(r, bd + (BLO - BHI));
        bl[2*np][0] = r[0]; bl[2*np][1] = r[1]; bl[2*np+1][0] = r[2]; bl[2*np+1][1] = r[3];
    }
#pragma unroll
    for (int mf = 0; mf < 4; mf++)
#pragma unroll
        for (int nf = 0; nf < 4; nf++) {
            mma16816(acc[mf][nf], ah[mf], bh[nf]);   // hi*hi
            mma16816(acc[mf][nf], ah[mf], bl[nf]);   // hi*lo
            mma16816(acc[mf][nf], al[mf], bh[nf]);   // lo*hi
        }
}

// ---------------------------------------------------------------------------
// Tensor-core GEMM: C = A[M,K] * B[N,K]^T  (bf16 split, fp32 accum)
//   MODE 0: proj (+bias[col])          MODE 1: V-proj (A=Wv, B=at) scatter
//   MODE 2: scores (scale/clip/mask)   MODE 3: PV -> ctx scatter
// ---------------------------------------------------------------------------
template<int MODE>
__global__ void __launch_bounds__(256, 1)
mma_gemm(const float* __restrict__ Ag, const float* __restrict__ Bg,
         const float* __restrict__ bias, const int* __restrict__ mask,
         float* __restrict__ Cg, int K, int lda, int ldb, int ldc)
{
    __shared__ __align__(16) char smem[SMEM_BYTES];
    const int tid = threadIdx.x;
    const int wid = tid >> 5;
    const int lane = tid & 31;
    const int g = lane >> 2, ti = lane & 3;
    const int mwb = (wid >> 2) * 64;      // warp m offset in tile
    const int nwb = (wid & 3) * 32;       // warp n offset in tile
    const uint32_t sbase = smem_to_u32(smem);

    const int m0 = blockIdx.y * 128;
    const int n0 = blockIdx.x * 128;
    const float* A = Ag;
    const float* Bm = Bg;
    int bb = 0, hh = 0;
    if (MODE == 2) {
        bb = blockIdx.z >> 4; hh = blockIdx.z & 15;
        A  += (size_t)bb * S_DIM * H_DIM + hh * HD_DIM;
        Bm += (size_t)bb * T_DIM * H_DIM + hh * HD_DIM;
    }
    if (MODE == 3) {
        bb = blockIdx.z >> 4; hh = blockIdx.z & 15;
        A  += (size_t)blockIdx.z * S_DIM * T_DIM;
        Bm += (size_t)blockIdx.z * HD_DIM * T_DIM;
    }

    float acc[4][4][4];
#pragma unroll
    for (int i = 0; i < 4; i++)
#pragma unroll
        for (int j = 0; j < 4; j++)
#pragma unroll
            for (int q = 0; q < 4; q++) acc[i][j][q] = 0.f;

    const int nchunk = K / BK;
    float4 aR[2], bR[2];

    // prologue: chunk 0 -> buffer 0
    ldg8(A,  lda, m0, 0, tid, aR);
    ldg8(Bm, ldb, n0, 0, tid, bR);
    split8(smem, AHI, ALO, tid, aR);
    split8(smem, BHI, BLO, tid, bR);
    __syncthreads();

    for (int c = 0; c < nchunk; c++) {
        const int nx = c + 1;
        if (nx < nchunk) {
            ldg8(A,  lda, m0, nx * BK, tid, aR);
            ldg8(Bm, ldb, n0, nx * BK, tid, bR);
        }
        compute_chunk(sbase + (c & 1) * BUFSZ, lane, mwb, nwb, acc);
        if (nx < nchunk) {
            char* nb = smem + (nx & 1) * BUFSZ;
            split8(nb, AHI, ALO, tid, aR);
            split8(nb, BHI, BLO, tid, bR);
        }
        __syncthreads();
    }

    // Epilogue: two passes through a 128x64 fp32 SMEM stage -> coalesced stores
    float* stage = (float*)smem;
#pragma unroll
    for (int p = 0; p < 2; p++) {
        if (p) __syncthreads();
#pragma unroll
        for (int mf = 0; mf < 4; mf++)
#pragma unroll
            for (int e = 0; e < 2; e++) {
                const int nf = 2 * p + e;
                const int row = mwb + mf * 16 + g;
                const int cm = (wid & 3) * 16 + e * 8 + ti * 2;
                *(float2*)&stage[row * STAGE_PITCH + cm] =
                    make_float2(acc[mf][nf][0], acc[mf][nf][1]);
                *(float2*)&stage[(row + 8) * STAGE_PITCH + cm] =
                    make_float2(acc[mf][nf][2], acc[mf][nf][3]);
            }
        __syncthreads();
#pragma unroll
        for (int it = 0; it < 8; it++) {
            const int lin = it * 1024 + tid * 4;
            const int row = lin >> 6;
            const int cm = lin & 63;
            const int col = ((cm >> 4) << 5) + (p << 4) + (cm & 15);
            float4 v = *(float4*)&stage[row * STAGE_PITCH + cm];
            if (MODE == 0) {
                float4 b4 = *(const float4*)(bias + n0 + col);
                float4 o = make_float4(v.x + b4.x, v.y + b4.y, v.z + b4.z, v.w + b4.w);
                *(float4*)(Cg + (size_t)(m0 + row) * ldc + n0 + col) = o;
            } else if (MODE == 1) {
                const int gr = m0 + row;                 // feature = h*128+d
                const int h = gr >> 7, d = gr & 127;
                const int n = n0 + col;                  // b*256+t
                const int b = n >> 8, t = n & 255;
                const float br = bias[gr];
                float4 o = make_float4(v.x + br, v.y + br, v.z + br, v.w + br);
                *(float4*)(Cg + ((size_t)(b * NHEAD + h) * HD_DIM + d) * T_DIM + t) = o;
            } else if (MODE == 2) {
                const float invs = 0.08838834764831845f;  // 1/sqrt(128)
                float vv[4] = {v.x, v.y, v.z, v.w};
                float4 o; float* po = &o.x;
                const int mb = bb * T_DIM + n0 + col;
#pragma unroll
                for (int j = 0; j < 4; j++) {
                    float s = vv[j] * invs;
                    s = fminf(fmaxf(s, -50.f), 50.f);
                    po[j] = mask[mb + j] ? s : -50.f;
                }
                *(float4*)(Cg + ((size_t)blockIdx.z * S_DIM + m0 + row) * T_DIM + n0 + col) = o;
            } else {
                *(float4*)(Cg + (size_t)(bb * S_DIM + m0 + row) * H_DIM + hh * HD_DIM + col) = v;
            }
        }
    }
}

// ---------------------------------------------------------------------------
// Softmax: one warp per row of 256 scores (in place)
// 131072 rows total = 16384 blocks x 8 warps
// ---------------------------------------------------------------------------
__global__ void softmax_kernel(float* __restrict__ S)
{
    int gw = (blockIdx.x * blockDim.x + threadIdx.x) >> 5;
    int lane = threadIdx.x & 31;
    float* p = S + (size_t)gw * T_DIM;

    float4 v0 = *(const float4*)(p + lane * 4);
    float4 v1 = *(const float4*)(p + 128 + lane * 4);
    float v[8] = {v0.x, v0.y, v0.z, v0.w, v1.x, v1.y, v1.z, v1.w};

    float mx = v[0];
#pragma unroll
    for (int i = 1; i < 8; i++) mx = fmaxf(mx, v[i]);
#pragma unroll
    for (int o = 16; o; o >>= 1) mx = fmaxf(mx, __shfl_xor_sync(0xffffffffu, mx, o));

    float s = 0.f;
#pragma unroll
    for (int i = 0; i < 8; i++) { v[i] = __expf(v[i] - mx); s += v[i]; }
#pragma unroll
    for (int o = 16; o; o >>= 1) s += __shfl_xor_sync(0xffffffffu, s, o);

    float inv = 1.f / s;
#pragma unroll
    for (int i = 0; i < 8; i++) v[i] *= inv;

    *(float4*)(p + lane * 4)       = make_float4(v[0], v[1], v[2], v[3]);
    *(float4*)(p + 128 + lane * 4) = make_float4(v[4], v[5], v[6], v[7]);
}

// ---------------------------------------------------------------------------
// LayerNorm (residual_scale applied), one block per row
// ---------------------------------------------------------------------------
__device__ __forceinline__ float block_sum(float v)
{
    __shared__ float red[8];
#pragma unroll
    for (int o = 16; o; o >>= 1) v += __shfl_xor_sync(0xffffffffu, v, o);
    int w = threadIdx.x >> 5;
    if ((threadIdx.x & 31) == 0) red[w] = v;
    __syncthreads();
    float t = (threadIdx.x < 8) ? red[threadIdx.x] : 0.f;
    if (threadIdx.x < 32) {
#pragma unroll
        for (int o = 4; o; o >>= 1) t += __shfl_xor_sync(0xffffffffu, t, o);
        if (threadIdx.x == 0) red[0] = t;
    }
    __syncthreads();
    float r = red[0];
    __syncthreads();
    return r;
}

__global__ void ln_kernel(const float* __restrict__ D, const float* __restrict__ gamma,
                          const float* __restrict__ beta, const float* __restrict__ rsp,
                          float* __restrict__ out)
{
    int row = blockIdx.x;
    int tid = threadIdx.x;
    float rs = fminf(fmaxf(rsp[0], 0.f), 0.3f);

    const float* d = D + (size_t)row * H_DIM;
    float4 u0 = *(const float4*)(d + tid * 4);
    float4 u1 = *(const float4*)(d + 1024 + tid * 4);
    float x[8] = {rs*u0.x, rs*u0.y, rs*u0.z, rs*u0.w,
                  rs*u1.x, rs*u1.y, rs*u1.z, rs*u1.w};

    float ps = 0.f;
#pragma unroll
    for (int i = 0; i < 8; i++) ps += x[i];
    float mean = block_sum(ps) * (1.f / 2048.f);

    float pv = 0.f;
#pragma unroll
    for (int i = 0; i < 8; i++) { float dd = x[i] - mean; pv += dd * dd; }
    float var = block_sum(pv) * (1.f / 2048.f);
    float inv = rsqrtf(var + 1e-5f);

    float4 gz0 = *(const float4*)(gamma + tid * 4);
    float4 gz1 = *(const float4*)(gamma + 1024 + tid * 4);
    float4 bz0 = *(const float4*)(beta + tid * 4);
    float4 bz1 = *(const float4*)(beta + 1024 + tid * 4);

    float* o = out + (size_t)row * H_DIM;
    *(float4*)(o + tid * 4) = make_float4(
        (x[0]-mean)*inv*gz0.x + bz0.x, (x[1]-mean)*inv*gz0.y + bz0.y,
        (x[2]-mean)*inv*gz0.z + bz0.z, (x[3]-mean)*inv*gz0.w + bz0.w);
    *(float4*)(o + 1024 + tid * 4) = make_float4(
        (x[4]-mean)*inv*gz1.x + bz1.x, (x[5]-mean)*inv*gz1.y + bz1.y,
        (x[6]-mean)*inv*gz1.z + bz1.z, (x[7]-mean)*inv*gz1.w + bz1.w);
}

// ---------------------------------------------------------------------------
// Launch
// ---------------------------------------------------------------------------
extern "C" void kernel_launch(void* const* d_in, const int* in_sizes, int n_in,
                              void* d_out, int out_size)
{
    const float* hs    = (const float*)d_in[0];
    const float* at    = (const float*)d_in[1];
    const int*   mask  = (const int*)  d_in[2];
    const float* Wq    = (const float*)d_in[3];
    const float* bq    = (const float*)d_in[4];
    const float* Wk    = (const float*)d_in[5];
    const float* bk    = (const float*)d_in[6];
    const float* Wv    = (const float*)d_in[7];
    const float* bv    = (const float*)d_in[8];
    const float* Wo    = (const float*)d_in[9];
    const float* bo    = (const float*)d_in[10];
    const float* gamma = (const float*)d_in[11];
    const float* beta  = (const float*)d_in[12];
    const float* rsp   = (const float*)d_in[13];
    float* out = (float*)d_out;

    float *Q, *Kb, *Vt, *Sb, *Cb, *Db;
    cudaGetSymbolAddress((void**)&Q,  g_Q);
    cudaGetSymbolAddress((void**)&Kb, g_K);
    cudaGetSymbolAddress((void**)&Vt, g_Vt);
    cudaGetSymbolAddress((void**)&Sb, g_S);
    cudaGetSymbolAddress((void**)&Cb, g_C);
    cudaGetSymbolAddress((void**)&Db, g_D);

    // Q projection: [8192,2048] = hs @ Wq^T + bq
    mma_gemm<0><<<dim3(16, 64, 1), 256>>>(hs, Wq, bq, nullptr, Q, 2048, 2048, 2048, 2048);
    // K projection: [1024,2048] = at @ Wk^T + bk
    mma_gemm<0><<<dim3(16, 8, 1), 256>>>(at, Wk, bk, nullptr, Kb, 2048, 2048, 2048, 2048);
    // V projection (A=Wv rows=features, B=at rows=tokens) -> Vt[b,h,d,t]
    mma_gemm<1><<<dim3(8, 16, 1), 256>>>(Wv, at, bv, nullptr, Vt, 2048, 2048, 2048, 0);
    // Scores per (b,h): [2048,256] = Q_bh @ K_bh^T, scale/clip/mask
    mma_gemm<2><<<dim3(2, 16, 64), 256>>>(Q, Kb, nullptr, mask, Sb, 128, 2048, 2048, 256);
    // Softmax over T=256 per row: 131072 rows = 16384 blocks x 8 warps
    softmax_kernel<<<16384, 256>>>(Sb);
    // PV per (b,h): [2048,128] = P @ Vt_bh^T -> ctx [b*S+s, h*HD+d]
    mma_gemm<3><<<dim3(1, 16, 64), 256>>>(Sb, Vt, nullptr, nullptr, Cb, 256, 256, 256, 0);
    // O projection
    mma_gemm<0><<<dim3(16, 64, 1), 256>>>(Cb, Wo, bo, nullptr, Db, 2048, 2048, 2048, 2048);
    // residual scale + LayerNorm
    ln_kernel<<<8192, 256>>>(Db, gamma, beta, rsp, out);
}

// round 5
// speedup vs baseline: 2.0716x; 1.1147x over previous
#include <cuda_runtime.h>
#include <cuda_bf16.h>
#include <cstdint>
#include <math.h>

#define B_DIM 4
#define S_DIM 2048
#define T_DIM 256
#define H_DIM 2048
#define NHEAD 16
#define HD_DIM 128

// GEMM tiling: 128x128 CTA tile, BK=16, 3-stage cp.async ring
#define BK 16
#define TILE_B 4096          // 128 rows x 32B (16 bf16)
#define STAGE_B 16384        // Ahi,Alo,Bhi,Blo
#define NSTAGE 3
#define SMEM_BYTES 49152
#define STAGE_PITCH 68       // fp32 epilogue staging pitch

// ---------------------------------------------------------------------------
// Persistent scratch (device globals)
// ---------------------------------------------------------------------------
__device__ __nv_bfloat16 g_hsh[8192*2048], g_hsl[8192*2048];
__device__ __nv_bfloat16 g_ath[1024*2048], g_atl[1024*2048];
__device__ __nv_bfloat16 g_Wqh[2048*2048], g_Wql[2048*2048];
__device__ __nv_bfloat16 g_Wkh[2048*2048], g_Wkl[2048*2048];
__device__ __nv_bfloat16 g_Wvh[2048*2048], g_Wvl[2048*2048];
__device__ __nv_bfloat16 g_Woh[2048*2048], g_Wol[2048*2048];
__device__ __nv_bfloat16 g_Qh[8192*2048],  g_Ql[8192*2048];
__device__ __nv_bfloat16 g_Kh[1024*2048],  g_Kl[1024*2048];
__device__ __nv_bfloat16 g_Vth[64*128*256], g_Vtl[64*128*256];
__device__ float         g_S[64u*2048u*256u];
__device__ __nv_bfloat16 g_Ph[64u*2048u*256u], g_Pl[64u*2048u*256u];
__device__ __nv_bfloat16 g_Ch[8192*2048],  g_Cl[8192*2048];
__device__ float         g_D[8192*2048];

// ---------------------------------------------------------------------------
// Helpers
// ---------------------------------------------------------------------------
__device__ __forceinline__ uint32_t smem_to_u32(const void* p) {
    uint32_t a;
    asm("{ .reg .u64 t; cvta.to.shared.u64 t, %1; cvt.u32.u64 %0, t; }" : "=r"(a) : "l"(p));
    return a;
}
__device__ __forceinline__ void cp16(uint32_t dst, const void* src) {
    asm volatile("cp.async.cg.shared.global [%0], [%1], 16;" :: "r"(dst), "l"(src));
}
#define CP_COMMIT() asm volatile("cp.async.commit_group;")
#define CP_WAIT1()  asm volatile("cp.async.wait_group 1;")

__device__ __forceinline__ void ldmx4(uint32_t* r, uint32_t addr) {
    asm volatile("ldmatrix.sync.aligned.m8n8.x4.shared.b16 {%0,%1,%2,%3}, [%4];"
                 : "=r"(r[0]), "=r"(r[1]), "=r"(r[2]), "=r"(r[3]) : "r"(addr));
}
__device__ __forceinline__ void mma16816(float* c, const uint32_t* a, const uint32_t* b) {
    asm volatile("mma.sync.aligned.m16n8k16.row.col.f32.bf16.bf16.f32 "
                 "{%0,%1,%2,%3}, {%4,%5,%6,%7}, {%8,%9}, {%0,%1,%2,%3};"
                 : "+f"(c[0]), "+f"(c[1]), "+f"(c[2]), "+f"(c[3])
                 : "r"(a[0]), "r"(a[1]), "r"(a[2]), "r"(a[3]), "r"(b[0]), "r"(b[1]));
}
__device__ __forceinline__ void split_pair(float x0, float x1, uint32_t& hi, uint32_t& lo) {
    __nv_bfloat162 h = __floats2bfloat162_rn(x0, x1);
    float r0 = x0 - __bfloat162float(h.x);
    float r1 = x1 - __bfloat162float(h.y);
    __nv_bfloat162 l = __floats2bfloat162_rn(r0, r1);
    hi = *(uint32_t*)&h;
    lo = *(uint32_t*)&l;
}
// XOR-swizzled address within a 128x16(bf16) tile, pitch 32B
__device__ __forceinline__ uint32_t swaddr(uint32_t tile, int row, int seg) {
    return tile + row * 32 + ((seg << 4) ^ ((row & 4) << 2));
}

// ---------------------------------------------------------------------------
// Pre-pass: split fp32 -> bf16 hi/lo (n multiple of 1024)
// ---------------------------------------------------------------------------
__global__ void split_kernel(const float* __restrict__ in,
                             __nv_bfloat16* __restrict__ hi,
                             __nv_bfloat16* __restrict__ lo)
{
    int idx = blockIdx.x * blockDim.x + threadIdx.x;
    float4 v = ((const float4*)in)[idx];
    uint32_t h0, l0, h1, l1;
    split_pair(v.x, v.y, h0, l0);
    split_pair(v.z, v.w, h1, l1);
    ((uint2*)hi)[idx] = make_uint2(h0, h1);
    ((uint2*)lo)[idx] = make_uint2(l0, l1);
}

// ---------------------------------------------------------------------------
// Tensor-core GEMM: C = A[M,K] * B[N,K]^T, operands pre-split bf16 hi/lo
//   MODE 0: proj+bias -> hi/lo out     MODE 1: V-proj -> Vt hi/lo scatter
//   MODE 2: scores -> fp32 (scale/clip/mask)
//   MODE 3: PV -> ctx hi/lo scatter    MODE 4: proj+bias -> fp32
// ---------------------------------------------------------------------------
template<int MODE>
__global__ void __launch_bounds__(256, 1)
mma_gemm(const __nv_bfloat16* __restrict__ Ah, const __nv_bfloat16* __restrict__ Al,
         const __nv_bfloat16* __restrict__ Bh, const __nv_bfloat16* __restrict__ Bl,
         const float* __restrict__ bias, const int* __restrict__ mask,
         float* __restrict__ Cf, __nv_bfloat16* __restrict__ Ch,
         __nv_bfloat16* __restrict__ Cl, int K, int lda, int ldb, int ldc)
{
    __shared__ __align__(16) char smem[SMEM_BYTES];
    const int tid = threadIdx.x;
    const int wid = tid >> 5;
    const int lane = tid & 31;
    const int g = lane >> 2, ti = lane & 3;
    const int mwb = (wid >> 2) * 64;
    const int nwb = (wid & 3) * 32;
    const uint32_t sbase = smem_to_u32(smem);

    const int m0 = blockIdx.y * 128;
    const int n0 = blockIdx.x * 128;
    int bb = 0, hh = 0;
    size_t aoff = 0, boff = 0;
    if (MODE == 2) {
        bb = blockIdx.z >> 4; hh = blockIdx.z & 15;
        aoff = (size_t)bb * S_DIM * H_DIM + hh * HD_DIM;
        boff = (size_t)bb * T_DIM * H_DIM + hh * HD_DIM;
    }
    if (MODE == 3) {
        bb = blockIdx.z >> 4; hh = blockIdx.z & 15;
        aoff = (size_t)blockIdx.z * S_DIM * T_DIM;
        boff = (size_t)blockIdx.z * HD_DIM * T_DIM;
    }
    const __nv_bfloat16* pAh = Ah + aoff;
    const __nv_bfloat16* pAl = Al + aoff;
    const __nv_bfloat16* pBh = Bh + boff;
    const __nv_bfloat16* pBl = Bl + boff;

    // cp.async thread mapping: row = tid>>1 (0..127), seg = tid&1
    const int crow = tid >> 1;
    const int cseg = tid & 1;
    const size_t asrc = (size_t)(m0 + crow) * lda + cseg * 8;
    const size_t bsrc = (size_t)(n0 + crow) * ldb + cseg * 8;
    const uint32_t cdst = swaddr(sbase, crow, cseg);   // offset within stage/tile

    const int nchunk = K / BK;

    auto issue = [&](int c) {
        const uint32_t st = (c % NSTAGE) * STAGE_B;
        const int kt = c * BK;
        cp16(cdst + st,              pAh + asrc + kt);
        cp16(cdst + st + TILE_B,     pAl + asrc + kt);
        cp16(cdst + st + 2*TILE_B,   pBh + bsrc + kt);
        cp16(cdst + st + 3*TILE_B,   pBl + bsrc + kt);
    };

    float acc[4][4][4];
#pragma unroll
    for (int i = 0; i < 4; i++)
#pragma unroll
        for (int j = 0; j < 4; j++)
#pragma unroll
            for (int q = 0; q < 4; q++) acc[i][j][q] = 0.f;

    // prologue: stages 0,1
    issue(0); CP_COMMIT();
    if (nchunk > 1) issue(1);
    CP_COMMIT();

    const int arow = lane & 15;
    const int aseg = lane >> 4;
    const int brow = (lane & 7) + ((lane >> 4) << 3);
    const int bseg = (lane >> 3) & 1;

    for (int c = 0; c < nchunk; c++) {
        CP_WAIT1();
        __syncthreads();
        if (c + 2 < nchunk) issue(c + 2);
        CP_COMMIT();

        const uint32_t sbuf = sbase + (c % NSTAGE) * STAGE_B;
        uint32_t ah[4][4], al[4][4], bh[4][2], bl[4][2];
#pragma unroll
        for (int mf = 0; mf < 4; mf++) {
            uint32_t ad = swaddr(sbuf, mwb + mf * 16 + arow, aseg);
            ldmx4(ah[mf], ad);
            ldmx4(al[mf], ad + TILE_B);
        }
#pragma unroll
        for (int np = 0; np < 2; np++) {
            uint32_t bd = swaddr(sbuf + 2*TILE_B, nwb + np * 16 + brow, bseg);
            uint32_t r[4];
            ldmx4(r, bd);
            bh[2*np][0] = r[0]; bh[2*np][1] = r[1]; bh[2*np+1][0] = r[2]; bh[2*np+1][1] = r[3];
            ldmx4(r, bd + TILE_B);
            bl[2*np][0] = r[0]; bl[2*np][1] = r[1]; bl[2*np+1][0] = r[2]; bl[2*np+1][1] = r[3];
        }
#pragma unroll
        for (int mf = 0; mf < 4; mf++)
#pragma unroll
            for (int nf = 0; nf < 4; nf++) {
                mma16816(acc[mf][nf], ah[mf], bh[nf]);
                mma16816(acc[mf][nf], ah[mf], bl[nf]);
                mma16816(acc[mf][nf], al[mf], bh[nf]);
            }
        __syncthreads();
    }

    // Epilogue: two passes through fp32 SMEM stage -> coalesced stores
    float* stage = (float*)smem;
#pragma unroll
    for (int p = 0; p < 2; p++) {
        if (p) __syncthreads();
#pragma unroll
        for (int mf = 0; mf < 4; mf++)
#pragma unroll
            for (int e = 0; e < 2; e++) {
                const int nf = 2 * p + e;
                const int row = mwb + mf * 16 + g;
                const int cm = (wid & 3) * 16 + e * 8 + ti * 2;
                *(float2*)&stage[row * STAGE_PITCH + cm] =
                    make_float2(acc[mf][nf][0], acc[mf][nf][1]);
                *(float2*)&stage[(row + 8) * STAGE_PITCH + cm] =
                    make_float2(acc[mf][nf][2], acc[mf][nf][3]);
            }
        __syncthreads();
#pragma unroll
        for (int it = 0; it < 8; it++) {
            const int lin = it * 1024 + tid * 4;
            const int row = lin >> 6;
            const int cm = lin & 63;
            const int col = ((cm >> 4) << 5) + (p << 4) + (cm & 15);
            float4 v = *(float4*)&stage[row * STAGE_PITCH + cm];
            if (MODE == 0 || MODE == 1 || MODE == 3) {
                float b0 = 0.f, b1 = 0.f, b2 = 0.f, b3 = 0.f;
                size_t off;
                if (MODE == 0) {
                    float4 b4 = *(const float4*)(bias + n0 + col);
                    b0 = b4.x; b1 = b4.y; b2 = b4.z; b3 = b4.w;
                    off = (size_t)(m0 + row) * ldc + n0 + col;
                } else if (MODE == 1) {
                    const int gr = m0 + row;             // feature = h*128+d
                    const int h = gr >> 7, d = gr & 127;
                    const int n = n0 + col;              // b*256+t
                    const int b = n >> 8, t = n & 255;
                    b0 = b1 = b2 = b3 = bias[gr];
                    off = ((size_t)(b * NHEAD + h) * HD_DIM + d) * T_DIM + t;
                } else {
                    off = (size_t)(bb * S_DIM + m0 + row) * H_DIM + hh * HD_DIM + col;
                }
                uint32_t h0, l0, h1, l1;
                split_pair(v.x + b0, v.y + b1, h0, l0);
                split_pair(v.z + b2, v.w + b3, h1, l1);
                *(uint2*)(Ch + off) = make_uint2(h0, h1);
                *(uint2*)(Cl + off) = make_uint2(l0, l1);
            } else if (MODE == 2) {
                const float invs = 0.08838834764831845f;  // 1/sqrt(128)
                float vv[4] = {v.x, v.y, v.z, v.w};
                float4 o; float* po = &o.x;
                const int mb = bb * T_DIM + n0 + col;
#pragma unroll
                for (int j = 0; j < 4; j++) {
                    float s = vv[j] * invs;
                    s = fminf(fmaxf(s, -50.f), 50.f);
                    po[j] = mask[mb + j] ? s : -50.f;
                }
                *(float4*)(Cf + ((size_t)blockIdx.z * S_DIM + m0 + row) * T_DIM + n0 + col) = o;
            } else {  // MODE 4: fp32 + bias
                float4 b4 = *(const float4*)(bias + n0 + col);
                float4 o = make_float4(v.x + b4.x, v.y + b4.y, v.z + b4.z, v.w + b4.w);
                *(float4*)(Cf + (size_t)(m0 + row) * ldc + n0 + col) = o;
            }
        }
    }
}

// ---------------------------------------------------------------------------
// Softmax: one warp per row of 256 scores; fp32 in, bf16 hi/lo out
// ---------------------------------------------------------------------------
__global__ void softmax_kernel(const float* __restrict__ S,
                               __nv_bfloat16* __restrict__ Ph,
                               __nv_bfloat16* __restrict__ Pl)
{
    int gw = (blockIdx.x * blockDim.x + threadIdx.x) >> 5;
    int lane = threadIdx.x & 31;
    const float* p = S + (size_t)gw * T_DIM;

    float4 v0 = *(const float4*)(p + lane * 4);
    float4 v1 = *(const float4*)(p + 128 + lane * 4);
    float v[8] = {v0.x, v0.y, v0.z, v0.w, v1.x, v1.y, v1.z, v1.w};

    float mx = v[0];
#pragma unroll
    for (int i = 1; i < 8; i++) mx = fmaxf(mx, v[i]);
#pragma unroll
    for (int o = 16; o; o >>= 1) mx = fmaxf(mx, __shfl_xor_sync(0xffffffffu, mx, o));

    float s = 0.f;
#pragma unroll
    for (int i = 0; i < 8; i++) { v[i] = __expf(v[i] - mx); s += v[i]; }
#pragma unroll
    for (int o = 16; o; o >>= 1) s += __shfl_xor_sync(0xffffffffu, s, o);

    float inv = 1.f / s;
#pragma unroll
    for (int i = 0; i < 8; i++) v[i] *= inv;

    uint32_t ph[4], pl[4];
    split_pair(v[0], v[1], ph[0], pl[0]);
    split_pair(v[2], v[3], ph[1], pl[1]);
    split_pair(v[4], v[5], ph[2], pl[2]);
    split_pair(v[6], v[7], ph[3], pl[3]);
    *(uint2*)(Ph + (size_t)gw * T_DIM + lane * 4)       = make_uint2(ph[0], ph[1]);
    *(uint2*)(Ph + (size_t)gw * T_DIM + 128 + lane * 4) = make_uint2(ph[2], ph[3]);
    *(uint2*)(Pl + (size_t)gw * T_DIM + lane * 4)       = make_uint2(pl[0], pl[1]);
    *(uint2*)(Pl + (size_t)gw * T_DIM + 128 + lane * 4) = make_uint2(pl[2], pl[3]);
}

// ---------------------------------------------------------------------------
// LayerNorm (residual_scale applied), one block per row
// ---------------------------------------------------------------------------
__device__ __forceinline__ float block_sum(float v)
{
    __shared__ float red[8];
#pragma unroll
    for (int o = 16; o; o >>= 1) v += __shfl_xor_sync(0xffffffffu, v, o);
    int w = threadIdx.x >> 5;
    if ((threadIdx.x & 31) == 0) red[w] = v;
    __syncthreads();
    float t = (threadIdx.x < 8) ? red[threadIdx.x] : 0.f;
    if (threadIdx.x < 32) {
#pragma unroll
        for (int o = 4; o; o >>= 1) t += __shfl_xor_sync(0xffffffffu, t, o);
        if (threadIdx.x == 0) red[0] = t;
    }
    __syncthreads();
    float r = red[0];
    __syncthreads();
    return r;
}

__global__ void ln_kernel(const float* __restrict__ D, const float* __restrict__ gamma,
                          const float* __restrict__ beta, const float* __restrict__ rsp,
                          float* __restrict__ out)
{
    int row = blockIdx.x;
    int tid = threadIdx.x;
    float rs = fminf(fmaxf(rsp[0], 0.f), 0.3f);

    const float* d = D + (size_t)row * H_DIM;
    float4 u0 = *(const float4*)(d + tid * 4);
    float4 u1 = *(const float4*)(d + 1024 + tid * 4);
    float x[8] = {rs*u0.x, rs*u0.y, rs*u0.z, rs*u0.w,
                  rs*u1.x, rs*u1.y, rs*u1.z, rs*u1.w};

    float ps = 0.f;
#pragma unroll
    for (int i = 0; i < 8; i++) ps += x[i];
    float mean = block_sum(ps) * (1.f / 2048.f);

    float pv = 0.f;
#pragma unroll
    for (int i = 0; i < 8; i++) { float dd = x[i] - mean; pv += dd * dd; }
    float var = block_sum(pv) * (1.f / 2048.f);
    float inv = rsqrtf(var + 1e-5f);

    float4 gz0 = *(const float4*)(gamma + tid * 4);
    float4 gz1 = *(const float4*)(gamma + 1024 + tid * 4);
    float4 bz0 = *(const float4*)(beta + tid * 4);
    float4 bz1 = *(const float4*)(beta + 1024 + tid * 4);

    float* o = out + (size_t)row * H_DIM;
    *(float4*)(o + tid * 4) = make_float4(
        (x[0]-mean)*inv*gz0.x + bz0.x, (x[1]-mean)*inv*gz0.y + bz0.y,
        (x[2]-mean)*inv*gz0.z + bz0.z, (x[3]-mean)*inv*gz0.w + bz0.w);
    *(float4*)(o + 1024 + tid * 4) = make_float4(
        (x[4]-mean)*inv*gz1.x + bz1.x, (x[5]-mean)*inv*gz1.y + bz1.y,
        (x[6]-mean)*inv*gz1.z + bz1.z, (x[7]-mean)*inv*gz1.w + bz1.w);
}

// ---------------------------------------------------------------------------
// Launch
// ---------------------------------------------------------------------------
extern "C" void kernel_launch(void* const* d_in, const int* in_sizes, int n_in,
                              void* d_out, int out_size)
{
    const float* hs    = (const float*)d_in[0];
    const float* at    = (const float*)d_in[1];
    const int*   mask  = (const int*)  d_in[2];
    const float* Wq    = (const float*)d_in[3];
    const float* bq    = (const float*)d_in[4];
    const float* Wk    = (const float*)d_in[5];
    const float* bk    = (const float*)d_in[6];
    const float* Wv    = (const float*)d_in[7];
    const float* bv    = (const float*)d_in[8];
    const float* Wo    = (const float*)d_in[9];
    const float* bo    = (const float*)d_in[10];
    const float* gamma = (const float*)d_in[11];
    const float* beta  = (const float*)d_in[12];
    const float* rsp   = (const float*)d_in[13];
    float* out = (float*)d_out;

    __nv_bfloat16 *hsh, *hsl, *ath, *atl, *Wqh, *Wql, *Wkh, *Wkl, *Wvh, *Wvl, *Woh, *Wol;
    __nv_bfloat16 *Qh, *Ql, *Kh, *Kl, *Vth, *Vtl, *Ph, *Pl, *Ch, *Cl;
    float *Sb, *Db;
    cudaGetSymbolAddress((void**)&hsh, g_hsh); cudaGetSymbolAddress((void**)&hsl, g_hsl);
    cudaGetSymbolAddress((void**)&ath, g_ath); cudaGetSymbolAddress((void**)&atl, g_atl);
    cudaGetSymbolAddress((void**)&Wqh, g_Wqh); cudaGetSymbolAddress((void**)&Wql, g_Wql);
    cudaGetSymbolAddress((void**)&Wkh, g_Wkh); cudaGetSymbolAddress((void**)&Wkl, g_Wkl);
    cudaGetSymbolAddress((void**)&Wvh, g_Wvh); cudaGetSymbolAddress((void**)&Wvl, g_Wvl);
    cudaGetSymbolAddress((void**)&Woh, g_Woh); cudaGetSymbolAddress((void**)&Wol, g_Wol);
    cudaGetSymbolAddress((void**)&Qh,  g_Qh);  cudaGetSymbolAddress((void**)&Ql,  g_Ql);
    cudaGetSymbolAddress((void**)&Kh,  g_Kh);  cudaGetSymbolAddress((void**)&Kl,  g_Kl);
    cudaGetSymbolAddress((void**)&Vth, g_Vth); cudaGetSymbolAddress((void**)&Vtl, g_Vtl);
    cudaGetSymbolAddress((void**)&Ph,  g_Ph);  cudaGetSymbolAddress((void**)&Pl,  g_Pl);
    cudaGetSymbolAddress((void**)&Ch,  g_Ch);  cudaGetSymbolAddress((void**)&Cl,  g_Cl);
    cudaGetSymbolAddress((void**)&Sb,  g_S);   cudaGetSymbolAddress((void**)&Db,  g_D);

    // Pre-pass: split all fp32 operands into bf16 hi/lo
    split_kernel<<<16384, 256>>>(hs, hsh, hsl);
    split_kernel<<<2048,  256>>>(at, ath, atl);
    split_kernel<<<4096,  256>>>(Wq, Wqh, Wql);
    split_kernel<<<4096,  256>>>(Wk, Wkh, Wkl);
    split_kernel<<<4096,  256>>>(Wv, Wvh, Wvl);
    split_kernel<<<4096,  256>>>(Wo, Woh, Wol);

    // Q projection -> Qh/Ql
    mma_gemm<0><<<dim3(16, 64, 1), 256>>>(hsh, hsl, Wqh, Wql, bq, nullptr,
                                          nullptr, Qh, Ql, 2048, 2048, 2048, 2048);
    // K projection -> Kh/Kl
    mma_gemm<0><<<dim3(16, 8, 1), 256>>>(ath, atl, Wkh, Wkl, bk, nullptr,
                                         nullptr, Kh, Kl, 2048, 2048, 2048, 2048);
    // V projection (A=Wv, B=at) -> Vt hi/lo [b,h,d,t]
    mma_gemm<1><<<dim3(8, 16, 1), 256>>>(Wvh, Wvl, ath, atl, bv, nullptr,
                                         nullptr, Vth, Vtl, 2048, 2048, 2048, 0);
    // Scores per (b,h) -> fp32 S
    mma_gemm<2><<<dim3(2, 16, 64), 256>>>(Qh, Ql, Kh, Kl, nullptr, mask,
                                          Sb, nullptr, nullptr, 128, 2048, 2048, 256);
    // Softmax: 131072 rows
    softmax_kernel<<<16384, 256>>>(Sb, Ph, Pl);
    // PV per (b,h) -> ctx hi/lo
    mma_gemm<3><<<dim3(1, 16, 64), 256>>>(Ph, Pl, Vth, Vtl, nullptr, nullptr,
                                          nullptr, Ch, Cl, 256, 256, 256, 0);
    // O projection -> fp32 D
    mma_gemm<4><<<dim3(16, 64, 1), 256>>>(Ch, Cl, Woh, Wol, bo, nullptr,
                                          Db, nullptr, nullptr, 2048, 2048, 2048, 2048);
    // residual scale + LayerNorm
    ln_kernel<<<8192, 256>>>(Db, gamma, beta, rsp, out);
}